// round 6
// baseline (speedup 1.0000x reference)
#include <cuda_runtime.h>

// out[b,o] = sum_{i<64, l<32} obs[b,i,l,o] * ctx[b, 31-l, i]
// obs[b] flattened over (i,l,o): offset = p*64 + o, p = i*32 + l (contiguous).
//
// Work unit = quarter-batch: (b, c) with chunk c owning pairs p in
// [c*512, (c+1)*512)  (i.e. i in [16c, 16c+16), all l). 8192 units over 148
// SMs -> 55.35 units/SM: per-SM imbalance ~1.8% (vs 7% at whole-b units).
// 128-thread CTAs, occ 16. Cross-chunk combine via atomicAdd after zero-init.

#define B_DIM 2048
#define R_DIM 32
#define O_DIM 64
#define PAIRS 2048             // 64*32
#define CHUNKS 4
#define CPAIRS (PAIRS / CHUNKS)     // 512 pairs per chunk
#define CI 16                       // i-columns per chunk
#define GROUPS 8
#define JITERS (CPAIRS / GROUPS)    // 64

__global__ void zero_out_kernel(float* __restrict__ out) {
    out[blockIdx.x * 512 + threadIdx.x] = 0.f;
}

__global__ __launch_bounds__(128, 16)
void cnnkf_kernel(const float* __restrict__ ctx,
                  const float* __restrict__ obs,
                  float* __restrict__ out) {
    __shared__ float s_ctx[R_DIM][CI];        // 2 KB: ctx[b, r, 16c + ii]
    __shared__ float s_part[GROUPS][O_DIM];   // 2 KB: per-group partials

    const int u   = blockIdx.x;
    const int b   = u >> 2;
    const int c   = u & 3;
    const int tid = threadIdx.x;

    const float* __restrict__ ctx_b = ctx + (size_t)b * (R_DIM * O_DIM) + c * CI;
    const float* __restrict__ obs_b = obs + (size_t)b * (size_t)(PAIRS * O_DIM);

    // Stage the 32x16 ctx sub-tile: thread t -> row t/16, col t%16 (4 passes).
    {
        const int row = tid >> 4;
        const int col = tid & 15;
        #pragma unroll
        for (int k = 0; k < R_DIM / 8; k++) {
            s_ctx[k * 8 + row][col] = ctx_b[(k * 8 + row) * O_DIM + col];
        }
    }
    __syncthreads();

    const int group = tid >> 4;   // 0..7
    const int olane = tid & 15;   // 0..15 -> o = 4*olane .. +3

    float4 acc = make_float4(0.f, 0.f, 0.f, 0.f);

    const float4* __restrict__ base = reinterpret_cast<const float4*>(obs_b);

    #pragma unroll 8
    for (int j = 0; j < JITERS; j++) {
        const int p = c * CPAIRS + j * GROUPS + group;  // warp -> contiguous 512B
        const float4 v = base[p * 16 + olane];
        const int l  = p & 31;
        const int ii = (p >> 5) & (CI - 1);
        const float cf = s_ctx[31 - l][ii];
        acc.x = fmaf(cf, v.x, acc.x);
        acc.y = fmaf(cf, v.y, acc.y);
        acc.z = fmaf(cf, v.z, acc.z);
        acc.w = fmaf(cf, v.w, acc.w);
    }

    *reinterpret_cast<float4*>(&s_part[group][olane * 4]) = acc;
    __syncthreads();

    // Cross-group reduce + global accumulate: 64 threads, one per o.
    if (tid < O_DIM) {
        float s = 0.f;
        #pragma unroll
        for (int g = 0; g < GROUPS; g++) s += s_part[g][tid];
        atomicAdd(&out[(size_t)b * O_DIM + tid], s);
    }
}

extern "C" void kernel_launch(void* const* d_in, const int* in_sizes, int n_in,
                              void* d_out, int out_size) {
    const float* ctx = (const float*)d_in[0];   // context      (B, R, O)
    const float* obs = (const float*)d_in[1];   // observation  (B, O, R, O)
    float* out = (float*)d_out;                  // (B, O)

    zero_out_kernel<<<(B_DIM * O_DIM) / 512, 512>>>(out);
    cnnkf_kernel<<<B_DIM * CHUNKS, 128>>>(ctx, obs, out);
}

// round 7
// speedup vs baseline: 1.0368x; 1.0368x over previous
#include <cuda_runtime.h>

// out[b,o] = sum_{i<64, l<32} obs[b,i,l,o] * ctx[b, 31-l, i]
// obs[b] flattened over (i,l,o) is contiguous: offset = p*64 + o, p = i*32 + l.
// One CTA per b. 256 threads = 16 groups x 16 lanes; lane owns 4 o-values.
// Warp = 2 adjacent groups -> one contiguous 512B LDG.128 transaction per step.
// __ldcs on the single-use obs stream (evict-first), unroll 16 for deep MLP.

#define B_DIM 2048
#define R_DIM 32
#define O_DIM 64
#define PAIRS 2048           // 64*32
#define GROUPS 16
#define PAIRS_PER_GROUP (PAIRS / GROUPS)   // 128

__global__ __launch_bounds__(256, 8)
void cnnkf_kernel(const float* __restrict__ ctx,
                  const float* __restrict__ obs,
                  float* __restrict__ out) {
    __shared__ float s_ctx[R_DIM * O_DIM];       // 8 KB: ctx[b] row-major [r][i]
    __shared__ float s_part[GROUPS][O_DIM];      // 4 KB: per-group partial sums

    const int b   = blockIdx.x;
    const int tid = threadIdx.x;

    const float* __restrict__ ctx_b = ctx + (size_t)b * (R_DIM * O_DIM);
    const float* __restrict__ obs_b = obs + (size_t)b * (size_t)(PAIRS * O_DIM);

    // Stage context slice (2048 floats) into smem, coalesced.
    #pragma unroll
    for (int k = 0; k < (R_DIM * O_DIM) / 256; k++) {
        s_ctx[k * 256 + tid] = ctx_b[k * 256 + tid];
    }
    __syncthreads();

    const int group = tid >> 4;   // 0..15
    const int olane = tid & 15;   // 0..15  -> o = olane*4 .. olane*4+3

    float4 acc = make_float4(0.f, 0.f, 0.f, 0.f);

    // float4 view: element (p, o4) at index p*16 + o4
    const float4* __restrict__ base = reinterpret_cast<const float4*>(obs_b);

    #pragma unroll 16
    for (int j = 0; j < PAIRS_PER_GROUP; j++) {
        const int p = j * GROUPS + group;          // warp (2 groups) -> contiguous 512B
        const float4 v = __ldcs(&base[p * 16 + olane]);   // evict-first stream
        const int l = p & 31;
        const int i = p >> 5;
        const float c = s_ctx[(31 - l) * O_DIM + i];      // broadcast within group
        acc.x = fmaf(c, v.x, acc.x);
        acc.y = fmaf(c, v.y, acc.y);
        acc.z = fmaf(c, v.z, acc.z);
        acc.w = fmaf(c, v.w, acc.w);
    }

    // Write partials
    *reinterpret_cast<float4*>(&s_part[group][olane * 4]) = acc;
    __syncthreads();

    // Cross-group reduction: 64 threads, one per o
    if (tid < O_DIM) {
        float s = 0.f;
        #pragma unroll
        for (int g = 0; g < GROUPS; g++) s += s_part[g][tid];
        out[(size_t)b * O_DIM + tid] = s;
    }
}

extern "C" void kernel_launch(void* const* d_in, const int* in_sizes, int n_in,
                              void* d_out, int out_size) {
    const float* ctx = (const float*)d_in[0];   // context      (B, R, O)
    const float* obs = (const float*)d_in[1];   // observation  (B, O, R, O)
    float* out = (float*)d_out;                  // (B, O)

    cnnkf_kernel<<<B_DIM, 256>>>(ctx, obs, out);
}

// round 12
// speedup vs baseline: 1.0398x; 1.0029x over previous
#include <cuda_runtime.h>

// out[b,o] = sum_{i<64, l<32} obs[b,i,l,o] * ctx[b, 31-l, i]
// obs[b] flattened over (i,l,o) is contiguous: float4 index = p*16 + o4,
// p = i*32 + l, o4 = o/4.
// One CTA per b, 256 threads = 8 warps. Per iteration each warp consumes
// 64 consecutive float4s (1024B): thread loads idx and idx+32 (two LDG.128).
// Both loads share the same o-range (low 4 bits of idx), so one accumulator.

#define B_DIM 2048
#define R_DIM 32
#define O_DIM 64
#define PAIRS 2048            // 64*32
#define NWARP 8
#define JITERS 64             // 2048 p's / (8 warps * 4 p's per warp-iter)

__global__ __launch_bounds__(256, 8)
void cnnkf_kernel(const float* __restrict__ ctx,
                  const float* __restrict__ obs,
                  float* __restrict__ out) {
    __shared__ float s_ctx[R_DIM * O_DIM];       // 8 KB: ctx[b] row-major [r][i]
    __shared__ float s_part[16][O_DIM];          // 4 KB: 16 partials per o

    const int b   = blockIdx.x;
    const int tid = threadIdx.x;

    const float* __restrict__ ctx_b = ctx + (size_t)b * (R_DIM * O_DIM);
    const float* __restrict__ obs_b = obs + (size_t)b * (size_t)(PAIRS * O_DIM);

    // Stage context slice (2048 floats) into smem, coalesced.
    #pragma unroll
    for (int k = 0; k < (R_DIM * O_DIM) / 256; k++) {
        s_ctx[k * 256 + tid] = ctx_b[k * 256 + tid];
    }
    __syncthreads();

    const int warp = tid >> 5;    // 0..7
    const int lane = tid & 31;    // 0..31
    const int o4   = lane & 15;   // o = o4*4 .. o4*4+3

    float4 acc = make_float4(0.f, 0.f, 0.f, 0.f);

    const float4* __restrict__ base = reinterpret_cast<const float4*>(obs_b);

    #pragma unroll 8
    for (int j = 0; j < JITERS; j++) {
        // Warp covers float4 indices [j*512 + warp*64, +64): 1024B contiguous.
        const int idx0 = j * 512 + warp * 64 + lane;
        const float4 v0 = __ldcs(&base[idx0]);        // p0 = idx0 >> 4
        const float4 v1 = __ldcs(&base[idx0 + 32]);   // p1 = p0 + 2
        const int p0 = idx0 >> 4;
        const int l0 = p0 & 31;
        const int i0 = p0 >> 5;
        const int p1 = p0 + 2;
        const int l1 = p1 & 31;
        const int i1 = p1 >> 5;
        const float c0 = s_ctx[(31 - l0) * O_DIM + i0];
        const float c1 = s_ctx[(31 - l1) * O_DIM + i1];
        acc.x = fmaf(c0, v0.x, acc.x);
        acc.y = fmaf(c0, v0.y, acc.y);
        acc.z = fmaf(c0, v0.z, acc.z);
        acc.w = fmaf(c0, v0.w, acc.w);
        acc.x = fmaf(c1, v1.x, acc.x);
        acc.y = fmaf(c1, v1.y, acc.y);
        acc.z = fmaf(c1, v1.z, acc.z);
        acc.w = fmaf(c1, v1.w, acc.w);
    }

    // 16 partial streams per o: row = warp*2 + (lane>>4)
    *reinterpret_cast<float4*>(&s_part[warp * 2 + (lane >> 4)][o4 * 4]) = acc;
    __syncthreads();

    // Cross-stream reduction: 64 threads, one per o
    if (tid < O_DIM) {
        float s = 0.f;
        #pragma unroll
        for (int g = 0; g < 16; g++) s += s_part[g][tid];
        out[(size_t)b * O_DIM + tid] = s;
    }
}

extern "C" void kernel_launch(void* const* d_in, const int* in_sizes, int n_in,
                              void* d_out, int out_size) {
    const float* ctx = (const float*)d_in[0];   // context      (B, R, O)
    const float* obs = (const float*)d_in[1];   // observation  (B, O, R, O)
    float* out = (float*)d_out;                  // (B, O)

    cnnkf_kernel<<<B_DIM, 256>>>(ctx, obs, out);
}

// round 14
// speedup vs baseline: 1.0556x; 1.0152x over previous
#include <cuda_runtime.h>

// out[b,o] = sum_{i<64, l<32} obs[b,i,l,o] * ctx[b, 31-l, i]
// obs[b] flattened over (i,l,o) is contiguous: float4 index = p*16 + o4,
// p = i*32 + l, o4 = o/4.
// One CTA per b, 256 threads = 8 warps. Per iteration each warp consumes
// 64 consecutive float4s (1024B): thread loads idx and idx+32 (two LDG.128).
// Lanes l and l+16 hold the SAME o-range -> one shfl folds the warp to 8
// partial streams, halving the smem epilogue. Output stored as float4.

#define B_DIM 2048
#define R_DIM 32
#define O_DIM 64
#define PAIRS 2048            // 64*32
#define JITERS 64             // 2048 p's / (8 warps * 4 p's per warp-iter)

__global__ __launch_bounds__(256, 8)
void cnnkf_kernel(const float* __restrict__ ctx,
                  const float* __restrict__ obs,
                  float* __restrict__ out) {
    __shared__ float s_ctx[R_DIM * O_DIM];       // 8 KB: ctx[b] row-major [r][i]
    __shared__ float s_part[8][O_DIM];           // 2 KB: 8 partials per o

    const int b   = blockIdx.x;
    const int tid = threadIdx.x;

    const float* __restrict__ ctx_b = ctx + (size_t)b * (R_DIM * O_DIM);
    const float* __restrict__ obs_b = obs + (size_t)b * (size_t)(PAIRS * O_DIM);

    // Stage context slice (2048 floats) into smem, coalesced.
    #pragma unroll
    for (int k = 0; k < (R_DIM * O_DIM) / 256; k++) {
        s_ctx[k * 256 + tid] = ctx_b[k * 256 + tid];
    }
    __syncthreads();

    const int warp = tid >> 5;    // 0..7
    const int lane = tid & 31;    // 0..31
    const int o4   = lane & 15;   // o = o4*4 .. o4*4+3

    float4 acc = make_float4(0.f, 0.f, 0.f, 0.f);

    const float4* __restrict__ base = reinterpret_cast<const float4*>(obs_b);

    #pragma unroll 8
    for (int j = 0; j < JITERS; j++) {
        // Warp covers float4 indices [j*512 + warp*64, +64): 1024B contiguous.
        const int idx0 = j * 512 + warp * 64 + lane;
        const float4 v0 = __ldcs(&base[idx0]);        // p0 = idx0 >> 4
        const float4 v1 = __ldcs(&base[idx0 + 32]);   // p1 = p0 + 2
        const int p0 = idx0 >> 4;
        const int l0 = p0 & 31;
        const int i0 = p0 >> 5;
        const int p1 = p0 + 2;
        const int l1 = p1 & 31;
        const int i1 = p1 >> 5;
        const float c0 = s_ctx[(31 - l0) * O_DIM + i0];
        const float c1 = s_ctx[(31 - l1) * O_DIM + i1];
        acc.x = fmaf(c0, v0.x, acc.x);
        acc.y = fmaf(c0, v0.y, acc.y);
        acc.z = fmaf(c0, v0.z, acc.z);
        acc.w = fmaf(c0, v0.w, acc.w);
        acc.x = fmaf(c1, v1.x, acc.x);
        acc.y = fmaf(c1, v1.y, acc.y);
        acc.z = fmaf(c1, v1.z, acc.z);
        acc.w = fmaf(c1, v1.w, acc.w);
    }

    // Intra-warp fold: lane and lane+16 hold the same o-range.
    acc.x += __shfl_down_sync(0xFFFFFFFFu, acc.x, 16);
    acc.y += __shfl_down_sync(0xFFFFFFFFu, acc.y, 16);
    acc.z += __shfl_down_sync(0xFFFFFFFFu, acc.z, 16);
    acc.w += __shfl_down_sync(0xFFFFFFFFu, acc.w, 16);

    if (lane < 16) {
        *reinterpret_cast<float4*>(&s_part[warp][o4 * 4]) = acc;
    }
    __syncthreads();

    // Cross-warp reduction: 64 threads, 16 of them emit one float4 STG each.
    if (tid < O_DIM) {
        float s = s_part[0][tid];
        #pragma unroll
        for (int g = 1; g < 8; g++) s += s_part[g][tid];
        s_part[0][tid] = s;          // reuse row 0 as the result row
    }
    __syncthreads();
    if (tid < 16) {
        reinterpret_cast<float4*>(out + (size_t)b * O_DIM)[tid] =
            reinterpret_cast<const float4*>(&s_part[0][0])[tid];
    }
}

extern "C" void kernel_launch(void* const* d_in, const int* in_sizes, int n_in,
                              void* d_out, int out_size) {
    const float* ctx = (const float*)d_in[0];   // context      (B, R, O)
    const float* obs = (const float*)d_in[1];   // observation  (B, O, R, O)
    float* out = (float*)d_out;                  // (B, O)

    cnnkf_kernel<<<B_DIM, 256>>>(ctx, obs, out);
}